// round 4
// baseline (speedup 1.0000x reference)
#include <cuda_runtime.h>

#define NT    8
#define NRES  500
#define NBINS 34
#define KCB   150.0f

__device__ __forceinline__ float ex2a(float x)  { float r; asm("ex2.approx.ftz.f32 %0, %1;"  : "=f"(r) : "f"(x)); return r; }
__device__ __forceinline__ float frcpa(float x) { float r; asm("rcp.approx.ftz.f32 %0, %1;"  : "=f"(r) : "f"(x)); return r; }
__device__ __forceinline__ float fsqrta(float x){ float r; asm("sqrt.approx.ftz.f32 %0, %1;" : "=f"(r) : "f"(x)); return r; }

__global__ __launch_bounds__(256) void force_folder_kernel(
    const float* __restrict__ coords,   // [NT, NRES, 3]
    const float* __restrict__ gw,       // [NRES, NRES, NBINS]  (i, j, b)
    const float* __restrict__ centres,  // [NBINS]
    const float* __restrict__ sigmas,   // [NBINS]
    float* __restrict__ out)            // [NT, NRES, 3]
{
    const int j   = blockIdx.x;
    const int tid = threadIdx.x;

    __shared__ float s_is[NBINS], s_mcs[NBINS], s_nis2[NBINS], s_c2[NBINS];
    __shared__ float s_cbj[NT * 3];
    __shared__ float s_part[NT * 3][8];

    if (tid < NBINS) {
        float s  = sigmas[tid];
        float c  = centres[tid];
        float is = 1.0f / s;
        s_is[tid]   = is;            // 1/sigma
        s_mcs[tid]  = -c * is;       // -c/sigma
        s_nis2[tid] = -(is * is);    // -1/sigma^2
        s_c2[tid]   = c * is * is;   //  c/sigma^2
    }
    if (tid < NT * 3) {
        int t = tid / 3, cc = tid - t * 3;
        s_cbj[tid] = coords[(t * NRES + j) * 3 + cc];
    }
    __syncthreads();

    float acc[NT][3];
    #pragma unroll
    for (int t = 0; t < NT; t++) { acc[t][0] = 0.f; acc[t][1] = 0.f; acc[t][2] = 0.f; }

    const float C = -0.72134752044f;  // -0.5 * log2(e)

    for (int i = tid; i < NRES; i += 256) {
        const float* wrow = gw + ((long)i * NRES + j) * NBINS;
        float d[NT], force[NT];
        #pragma unroll
        for (int t = 0; t < NT; t++) {
            const float* ci = coords + (t * NRES + i) * 3;
            float dx = s_cbj[t * 3 + 0] - ci[0];
            float dy = s_cbj[t * 3 + 1] - ci[1];
            float dz = s_cbj[t * 3 + 2] - ci[2];
            float ss = fmaf(dx, dx, fmaf(dy, dy, dz * dz));
            float dd = fsqrta(ss);
            dd = fminf(fmaxf(dd, 0.1f), 40.0f);   // clip(dist, 0.1, FORCE_CUTOFF)
            d[t] = dd;
            force[t] = 0.0f;
        }

        #pragma unroll 2
        for (int b = 0; b < NBINS; b++) {
            float is   = s_is[b];
            float mcs  = s_mcs[b];
            float nis2 = s_nis2[b];
            float c2   = s_c2[b];
            float ws   = wrow[b] * is;   // w/sigma, shared across all 8 trajs
            #pragma unroll
            for (int t = 0; t < NT; t++) {
                float q = fmaf(d[t], is,   mcs);   // (d - c)/sigma
                float p = fmaf(d[t], nis2, c2);    // -(d - c)/sigma^2
                float e = ex2a(q * q * C);         // exp(-0.5 q^2)
                force[t] = fmaf(p * ws, e, force[t]);
            }
        }

        #pragma unroll
        for (int t = 0; t < NT; t++) {
            const float* ci = coords + (t * NRES + i) * 3;
            float coef = -KCB * force[t] * frcpa(d[t]);  // -K*force/dist
            acc[t][0] = fmaf(coef, s_cbj[t * 3 + 0] - ci[0], acc[t][0]);
            acc[t][1] = fmaf(coef, s_cbj[t * 3 + 1] - ci[1], acc[t][1]);
            acc[t][2] = fmaf(coef, s_cbj[t * 3 + 2] - ci[2], acc[t][2]);
        }
    }

    // Block reduction over i: shfl within warp, then smem across 8 warps.
    const int lane = tid & 31, warp = tid >> 5;
    #pragma unroll
    for (int t = 0; t < NT; t++) {
        #pragma unroll
        for (int c = 0; c < 3; c++) {
            float v = acc[t][c];
            v += __shfl_down_sync(0xffffffffu, v, 16);
            v += __shfl_down_sync(0xffffffffu, v, 8);
            v += __shfl_down_sync(0xffffffffu, v, 4);
            v += __shfl_down_sync(0xffffffffu, v, 2);
            v += __shfl_down_sync(0xffffffffu, v, 1);
            if (lane == 0) s_part[t * 3 + c][warp] = v;
        }
    }
    __syncthreads();
    if (tid < NT * 3) {
        float s = 0.f;
        #pragma unroll
        for (int w = 0; w < 8; w++) s += s_part[tid][w];
        int t = tid / 3, cc = tid - t * 3;
        out[(t * NRES + j) * 3 + cc] = s;
    }
}

extern "C" void kernel_launch(void* const* d_in, const int* in_sizes, int n_in,
                              void* d_out, int out_size) {
    const float* coords  = (const float*)d_in[0];
    const float* gw      = (const float*)d_in[1];
    const float* centres = (const float*)d_in[2];
    const float* sigmas  = (const float*)d_in[3];
    force_folder_kernel<<<NRES, 256>>>(coords, gw, centres, sigmas, (float*)d_out);
}

// round 5
// speedup vs baseline: 1.0145x; 1.0145x over previous
#include <cuda_runtime.h>

#define NT    8
#define NRES  500
#define NBINS 34
#define KCB   150.0f

__device__ __forceinline__ float ex2a(float x)  { float r; asm("ex2.approx.ftz.f32 %0, %1;"  : "=f"(r) : "f"(x)); return r; }
__device__ __forceinline__ float frcpa(float x) { float r; asm("rcp.approx.ftz.f32 %0, %1;"  : "=f"(r) : "f"(x)); return r; }
__device__ __forceinline__ float fsqrta(float x){ float r; asm("sqrt.approx.ftz.f32 %0, %1;" : "=f"(r) : "f"(x)); return r; }

__global__ __launch_bounds__(256) void force_folder_kernel(
    const float* __restrict__ coords,   // [NT, NRES, 3]
    const float* __restrict__ gw,       // [NRES, NRES, NBINS]  (i, j, b)
    const float* __restrict__ centres,  // [NBINS]
    const float* __restrict__ sigmas,   // [NBINS]
    float* __restrict__ out)            // [NT, NRES, 3]
{
    const int j   = blockIdx.x;
    const int tid = threadIdx.x;

    __shared__ float s_is[NBINS], s_mcs[NBINS], s_nis2[NBINS], s_c2[NBINS];
    __shared__ float s_cbj[NT * 3];
    __shared__ float s_part[NT * 3][8];

    if (tid < NBINS) {
        float s  = sigmas[tid];
        float c  = centres[tid];
        float is = 1.0f / s;
        s_is[tid]   = is;            // 1/sigma
        s_mcs[tid]  = -c * is;       // -c/sigma
        s_nis2[tid] = -(is * is);    // -1/sigma^2
        s_c2[tid]   = c * is * is;   //  c/sigma^2
    }
    if (tid < NT * 3) {
        int t = tid / 3, cc = tid - t * 3;
        s_cbj[tid] = coords[(t * NRES + j) * 3 + cc];
    }
    __syncthreads();

    float acc[NT][3];
    #pragma unroll
    for (int t = 0; t < NT; t++) { acc[t][0] = 0.f; acc[t][1] = 0.f; acc[t][2] = 0.f; }

    const float C = -0.72134752044f;  // -0.5 * log2(e)

    for (int i = tid; i < NRES; i += 256) {
        const float* wrow = gw + ((long)i * NRES + j) * NBINS;
        float d[NT], force[NT];
        #pragma unroll
        for (int t = 0; t < NT; t++) {
            const float* ci = coords + (t * NRES + i) * 3;
            float dx = s_cbj[t * 3 + 0] - ci[0];
            float dy = s_cbj[t * 3 + 1] - ci[1];
            float dz = s_cbj[t * 3 + 2] - ci[2];
            float ss = fmaf(dx, dx, fmaf(dy, dy, dz * dz));
            float dd = fsqrta(ss);
            dd = fminf(fmaxf(dd, 0.1f), 40.0f);   // clip(dist, 0.1, FORCE_CUTOFF)
            d[t] = dd;
            force[t] = 0.0f;
        }

        #pragma unroll 2
        for (int b = 0; b < NBINS; b++) {
            float is   = s_is[b];
            float mcs  = s_mcs[b];
            float nis2 = s_nis2[b];
            float c2   = s_c2[b];
            float ws   = wrow[b] * is;   // w/sigma, shared across all 8 trajs
            #pragma unroll
            for (int t = 0; t < NT; t++) {
                float q = fmaf(d[t], is,   mcs);   // (d - c)/sigma
                float p = fmaf(d[t], nis2, c2);    // -(d - c)/sigma^2
                float e = ex2a(q * q * C);         // exp(-0.5 q^2)
                force[t] = fmaf(p * ws, e, force[t]);
            }
        }

        #pragma unroll
        for (int t = 0; t < NT; t++) {
            const float* ci = coords + (t * NRES + i) * 3;
            float coef = -KCB * force[t] * frcpa(d[t]);  // -K*force/dist
            acc[t][0] = fmaf(coef, s_cbj[t * 3 + 0] - ci[0], acc[t][0]);
            acc[t][1] = fmaf(coef, s_cbj[t * 3 + 1] - ci[1], acc[t][1]);
            acc[t][2] = fmaf(coef, s_cbj[t * 3 + 2] - ci[2], acc[t][2]);
        }
    }

    // Block reduction over i: shfl within warp, then smem across 8 warps.
    const int lane = tid & 31, warp = tid >> 5;
    #pragma unroll
    for (int t = 0; t < NT; t++) {
        #pragma unroll
        for (int c = 0; c < 3; c++) {
            float v = acc[t][c];
            v += __shfl_down_sync(0xffffffffu, v, 16);
            v += __shfl_down_sync(0xffffffffu, v, 8);
            v += __shfl_down_sync(0xffffffffu, v, 4);
            v += __shfl_down_sync(0xffffffffu, v, 2);
            v += __shfl_down_sync(0xffffffffu, v, 1);
            if (lane == 0) s_part[t * 3 + c][warp] = v;
        }
    }
    __syncthreads();
    if (tid < NT * 3) {
        float s = 0.f;
        #pragma unroll
        for (int w = 0; w < 8; w++) s += s_part[tid][w];
        int t = tid / 3, cc = tid - t * 3;
        out[(t * NRES + j) * 3 + cc] = s;
    }
}

extern "C" void kernel_launch(void* const* d_in, const int* in_sizes, int n_in,
                              void* d_out, int out_size) {
    const float* coords  = (const float*)d_in[0];
    const float* gw      = (const float*)d_in[1];
    const float* centres = (const float*)d_in[2];
    const float* sigmas  = (const float*)d_in[3];
    force_folder_kernel<<<NRES, 256>>>(coords, gw, centres, sigmas, (float*)d_out);
}